// round 7
// baseline (speedup 1.0000x reference)
#include <cuda_runtime.h>
#include <cuda_bf16.h>
#include <math.h>
#include <stdint.h>

// ---------------------------------------------------------------------------
// Problem dims (fixed)
// ---------------------------------------------------------------------------
#define BB 4
#define TQ 1024
#define TK 1024
#define DD 1024
#define HH 16
#define DK 64
#define DV 64
#define MROWS (BB * TQ)          // 4096
#define BH (BB * HH)             // 64

// ---------------------------------------------------------------------------
// Scratch (device globals — no allocations allowed)
// ---------------------------------------------------------------------------
__device__ float g_x2 [MROWS * DD];
__device__ float g_h  [MROWS * DD];
// bf16 hi/lo activation buffers
__device__ __nv_bfloat16 g_xhi[MROWS * DD];
__device__ __nv_bfloat16 g_xlo[MROWS * DD];
__device__ __nv_bfloat16 g_yhi[MROWS * DD];
__device__ __nv_bfloat16 g_ylo[MROWS * DD];
__device__ __nv_bfloat16 g_phi[MROWS * DD];
__device__ __nv_bfloat16 g_plo[MROWS * DD];
// weight (transposed) buffers
__device__ __nv_bfloat16 g_bhi[DD * DD];
__device__ __nv_bfloat16 g_blo[DD * DD];
// q/k/v bf16 (written directly by GEMM epilogue)
__device__ __nv_bfloat16 g_qhi[MROWS * DD];
__device__ __nv_bfloat16 g_qlo[MROWS * DD];
__device__ __nv_bfloat16 g_khi[MROWS * DD];
__device__ __nv_bfloat16 g_klo[MROWS * DD];
__device__ __nv_bfloat16 g_vhi[MROWS * DD];
__device__ __nv_bfloat16 g_vlo[MROWS * DD];

// ---------------------------------------------------------------------------
// PTX helpers (sm_80+ baseline features only)
// ---------------------------------------------------------------------------
__device__ __forceinline__ uint32_t smem_u32(const void* p) {
    uint32_t a;
    asm("{ .reg .u64 t; cvta.to.shared.u64 t, %1; cvt.u32.u64 %0, t; }" : "=r"(a) : "l"(p));
    return a;
}
__device__ __forceinline__ void cpasync16(uint32_t dst, const void* src) {
    asm volatile("cp.async.cg.shared.global [%0], [%1], 16;" :: "r"(dst), "l"(src) : "memory");
}
#define CP_COMMIT() asm volatile("cp.async.commit_group;" ::: "memory")
#define CP_WAIT(n)  asm volatile("cp.async.wait_group %0;" :: "n"(n) : "memory")

__device__ __forceinline__ void ldm4(uint32_t* r, uint32_t addr) {
    asm volatile("ldmatrix.sync.aligned.m8n8.x4.shared.b16 {%0,%1,%2,%3}, [%4];"
        : "=r"(r[0]), "=r"(r[1]), "=r"(r[2]), "=r"(r[3]) : "r"(addr));
}
__device__ __forceinline__ void ldm4t(uint32_t* r, uint32_t addr) {
    asm volatile("ldmatrix.sync.aligned.m8n8.x4.trans.shared.b16 {%0,%1,%2,%3}, [%4];"
        : "=r"(r[0]), "=r"(r[1]), "=r"(r[2]), "=r"(r[3]) : "r"(addr));
}
__device__ __forceinline__ void mma16816(float* d, const uint32_t* a, const uint32_t* b) {
    asm volatile("mma.sync.aligned.m16n8k16.row.col.f32.bf16.bf16.f32 "
        "{%0,%1,%2,%3}, {%4,%5,%6,%7}, {%8,%9}, {%0,%1,%2,%3};"
        : "+f"(d[0]), "+f"(d[1]), "+f"(d[2]), "+f"(d[3])
        : "r"(a[0]), "r"(a[1]), "r"(a[2]), "r"(a[3]), "r"(b[0]), "r"(b[1]));
}

// ---------------------------------------------------------------------------
// LayerNorm + ReLU -> bf16 hi/lo (fused; no fp32 intermediate)
// ---------------------------------------------------------------------------
__global__ void ln_relu_split_kernel(const float* __restrict__ in,
                                     const float* __restrict__ gamma,
                                     const float* __restrict__ beta,
                                     __nv_bfloat16* __restrict__ hi,
                                     __nv_bfloat16* __restrict__ lo) {
    int row = blockIdx.x;
    int tid = threadIdx.x;
    const float* p = in + (size_t)row * DD + tid * 4;
    float4 xv = *(const float4*)p;

    float s  = xv.x + xv.y + xv.z + xv.w;
    float ss = xv.x*xv.x + xv.y*xv.y + xv.z*xv.z + xv.w*xv.w;
    #pragma unroll
    for (int off = 16; off > 0; off >>= 1) {
        s  += __shfl_xor_sync(0xffffffffu, s,  off);
        ss += __shfl_xor_sync(0xffffffffu, ss, off);
    }
    __shared__ float sbuf[8], ssbuf[8];
    __shared__ float smean, sinv;
    int lane = tid & 31, warp = tid >> 5;
    if (lane == 0) { sbuf[warp] = s; ssbuf[warp] = ss; }
    __syncthreads();
    if (tid == 0) {
        float ts = 0.f, tss = 0.f;
        #pragma unroll
        for (int i = 0; i < 8; i++) { ts += sbuf[i]; tss += ssbuf[i]; }
        float mean = ts * (1.0f / DD);
        float var  = tss * (1.0f / DD) - mean * mean;
        smean = mean;
        sinv  = rsqrtf(var + 1e-5f);
    }
    __syncthreads();
    float m = smean, inv = sinv;

    int c = tid * 4;
    float4 g4 = *(const float4*)(gamma + c);
    float4 b4 = *(const float4*)(beta  + c);
    float o0 = fmaxf(0.f, (xv.x - m) * inv * g4.x + b4.x);
    float o1 = fmaxf(0.f, (xv.y - m) * inv * g4.y + b4.y);
    float o2 = fmaxf(0.f, (xv.z - m) * inv * g4.z + b4.z);
    float o3 = fmaxf(0.f, (xv.w - m) * inv * g4.w + b4.w);

    __nv_bfloat162 h0 = __floats2bfloat162_rn(o0, o1);
    __nv_bfloat162 h1 = __floats2bfloat162_rn(o2, o3);
    __nv_bfloat162 l0 = __floats2bfloat162_rn(o0 - __bfloat162float(h0.x),
                                              o1 - __bfloat162float(h0.y));
    __nv_bfloat162 l1 = __floats2bfloat162_rn(o2 - __bfloat162float(h1.x),
                                              o3 - __bfloat162float(h1.y));
    size_t base = (size_t)row * DD + c;
    *(__nv_bfloat162*)(hi + base)     = h0;
    *(__nv_bfloat162*)(hi + base + 2) = h1;
    *(__nv_bfloat162*)(lo + base)     = l0;
    *(__nv_bfloat162*)(lo + base + 2) = l1;
}

// ---------------------------------------------------------------------------
// Transpose + split: W[K=1024, N=1024] fp32 -> Wt_hi/Wt_lo [N, K] bf16
// ---------------------------------------------------------------------------
__global__ void transpose_split_kernel(const float* __restrict__ W,
                                       __nv_bfloat16* __restrict__ hi,
                                       __nv_bfloat16* __restrict__ lo) {
    __shared__ float tile[32][33];
    int tx = threadIdx.x, ty = threadIdx.y;          // 32 x 8
    int n0 = blockIdx.x * 32, k0 = blockIdx.y * 32;
    #pragma unroll
    for (int i = 0; i < 4; i++) {
        int kr = ty + i * 8;
        tile[kr][tx] = W[(size_t)(k0 + kr) * DD + n0 + tx];
    }
    __syncthreads();
    #pragma unroll
    for (int i = 0; i < 4; i++) {
        int nr = ty + i * 8;
        float v = tile[tx][nr];
        __nv_bfloat16 h = __float2bfloat16_rn(v);
        __nv_bfloat16 l = __float2bfloat16_rn(v - __bfloat162float(h));
        hi[(size_t)(n0 + nr) * DD + k0 + tx] = h;
        lo[(size_t)(n0 + nr) * DD + k0 + tx] = l;
    }
}

// ---------------------------------------------------------------------------
// HMMA GEMM: C[4096,1024] = A @ Wt^T (+bias, +res).  3-term hi/lo Markidis.
// CTA tile 256x128, BK=64, double-buffered cp.async, 16 warps (4M x 4N),
// warp tile 64x32 (acc = 64 regs/thread — no spill).  Grid (8,16) = 128 CTAs.
// smem: Ah[2]=64K  Al[2]=64K  Bh[2]=32K  Bl[2]=32K  -> 192K
// ---------------------------------------------------------------------------
#define GA_OFF(buf)  ((buf) * 32768)
#define GAL_OFF(buf) (65536 + (buf) * 32768)
#define GB_OFF(buf)  (131072 + (buf) * 16384)
#define GBL_OFF(buf) (163840 + (buf) * 16384)
#define GT_SMEM 196608
#define GT_THREADS 512

struct GPtrs { const char *ahi, *alo, *bhi, *blo; };

__device__ __forceinline__ void gt_load_chunk(uint32_t sb, int buf,
                                              const GPtrs& g, int chunk, int tid) {
    size_t kbyte = (size_t)chunk * 128;
    // A tiles: 256 rows x 128B (hi, lo) = 2048 x 16B each
    #pragma unroll
    for (int t = 0; t < 2; t++) {
        uint32_t base = sb + (t ? GAL_OFF(buf) : GA_OFF(buf));
        const char* src = t ? g.alo : g.ahi;
        #pragma unroll
        for (int it = 0; it < 4; it++) {
            int idx = tid + it * GT_THREADS;        // 0..2047
            int r = idx >> 3;
            int c16 = idx & 7;
            uint32_t so = (uint32_t)(r * 128 + c16 * 16);
            uint32_t sw = so ^ ((so >> 3) & 0x70);
            cpasync16(base + sw, src + (size_t)r * 2048 + kbyte + c16 * 16);
        }
    }
    // B tiles: 128 rows x 128B (hi, lo) = 1024 x 16B each
    #pragma unroll
    for (int t = 0; t < 2; t++) {
        uint32_t base = sb + (t ? GBL_OFF(buf) : GB_OFF(buf));
        const char* src = t ? g.blo : g.bhi;
        #pragma unroll
        for (int it = 0; it < 2; it++) {
            int idx = tid + it * GT_THREADS;        // 0..1023
            int r = idx >> 3;
            int c16 = idx & 7;
            uint32_t so = (uint32_t)(r * 128 + c16 * 16);
            uint32_t sw = so ^ ((so >> 3) & 0x70);
            cpasync16(base + sw, src + (size_t)r * 2048 + kbyte + c16 * 16);
        }
    }
}

__global__ void __launch_bounds__(GT_THREADS, 1)
gemm_hmma(const __nv_bfloat16* __restrict__ Ahi, const __nv_bfloat16* __restrict__ Alo,
          const __nv_bfloat16* __restrict__ Bhi, const __nv_bfloat16* __restrict__ Blo,
          const float* __restrict__ bias, const float* __restrict__ res,
          float* __restrict__ C,
          __nv_bfloat16* __restrict__ Chi, __nv_bfloat16* __restrict__ Clo) {
    extern __shared__ char smem[];
    uint32_t sb = smem_u32(smem);
    int tid = threadIdx.x;
    int lane = tid & 31;
    int wid = tid >> 5;              // 0..15
    int wm = wid & 3;                // 0..3 (M, 64 rows each)
    int wn = wid >> 2;               // 0..3 (N, 32 cols each)

    int n0 = blockIdx.x * 128;
    int m0 = blockIdx.y * 256;

    GPtrs g;
    g.ahi = (const char*)(Ahi + (size_t)m0 * DD);
    g.alo = (const char*)(Alo + (size_t)m0 * DD);
    g.bhi = (const char*)(Bhi + (size_t)n0 * DD);
    g.blo = (const char*)(Blo + (size_t)n0 * DD);

    float acc[4][4][4];
    #pragma unroll
    for (int i = 0; i < 4; i++)
        #pragma unroll
        for (int j = 0; j < 4; j++)
            #pragma unroll
            for (int r = 0; r < 4; r++) acc[i][j][r] = 0.f;

    uint32_t aRow = (uint32_t)(wm * 64 + (lane & 15));
    uint32_t xorb = (uint32_t)((lane & 7) * 16);
    uint32_t aHi  = (uint32_t)(((lane >> 4) & 1) * 16);
    uint32_t bRow = (uint32_t)(wn * 32 + ((lane >> 4) & 1) * 8 + (lane & 7));
    uint32_t bHi  = (uint32_t)(((lane >> 3) & 1) * 16);

    gt_load_chunk(sb, 0, g, 0, tid);
    CP_COMMIT();

    #pragma unroll 1
    for (int c = 0; c < 16; c++) {
        int buf = c & 1;
        if (c < 15) {
            gt_load_chunk(sb, buf ^ 1, g, c + 1, tid);
            CP_COMMIT();
            CP_WAIT(1);
        } else {
            CP_WAIT(0);
        }
        __syncthreads();

        uint32_t tAh = sb + GA_OFF(buf);
        uint32_t tAl = sb + GAL_OFF(buf);
        uint32_t tBh = sb + GB_OFF(buf);
        uint32_t tBl = sb + GBL_OFF(buf);

        #pragma unroll
        for (int ks = 0; ks < 4; ks++) {
            uint32_t ka = ((uint32_t)(ks * 32) + aHi) ^ xorb;
            uint32_t kb = ((uint32_t)(ks * 32) + bHi) ^ xorb;

            uint32_t Ah[4][4], Al[4][4], Bh[2][4], Bl[2][4];
            #pragma unroll
            for (int i = 0; i < 4; i++) {
                uint32_t ro = (aRow + 16 * i) * 128;
                ldm4(Ah[i], tAh + ro + ka);
                ldm4(Al[i], tAl + ro + ka);
            }
            #pragma unroll
            for (int jp = 0; jp < 2; jp++) {
                uint32_t ro = (bRow + 16 * jp) * 128;
                ldm4(Bh[jp], tBh + ro + kb);
                ldm4(Bl[jp], tBl + ro + kb);
            }
            #pragma unroll
            for (int i = 0; i < 4; i++) {
                #pragma unroll
                for (int j = 0; j < 4; j++) {
                    const uint32_t* bh = &Bh[j >> 1][(j & 1) * 2];
                    const uint32_t* bl = &Bl[j >> 1][(j & 1) * 2];
                    mma16816(acc[i][j], Ah[i], bh);
                    mma16816(acc[i][j], Ah[i], bl);
                    mma16816(acc[i][j], Al[i], bh);
                }
            }
        }
        __syncthreads();
    }

    int rbase = m0 + wm * 64 + (lane >> 2);
    int cbase = n0 + wn * 32 + (lane & 3) * 2;
    #pragma unroll
    for (int j = 0; j < 4; j++) {
        int cc = cbase + 8 * j;
        float2 b2 = *(const float2*)(bias + cc);
        #pragma unroll
        for (int i = 0; i < 4; i++) {
            int r = rbase + 16 * i;
            float2 o0 = {acc[i][j][0] + b2.x, acc[i][j][1] + b2.y};
            float2 o1 = {acc[i][j][2] + b2.x, acc[i][j][3] + b2.y};
            size_t off0 = (size_t)r * DD + cc;
            size_t off1 = (size_t)(r + 8) * DD + cc;
            if (Chi) {
                __nv_bfloat162 h0 = __floats2bfloat162_rn(o0.x, o0.y);
                __nv_bfloat162 h1 = __floats2bfloat162_rn(o1.x, o1.y);
                __nv_bfloat162 l0 = __floats2bfloat162_rn(
                    o0.x - __bfloat162float(h0.x), o0.y - __bfloat162float(h0.y));
                __nv_bfloat162 l1 = __floats2bfloat162_rn(
                    o1.x - __bfloat162float(h1.x), o1.y - __bfloat162float(h1.y));
                *(__nv_bfloat162*)(Chi + off0) = h0;
                *(__nv_bfloat162*)(Chi + off1) = h1;
                *(__nv_bfloat162*)(Clo + off0) = l0;
                *(__nv_bfloat162*)(Clo + off1) = l1;
            } else {
                if (res) {
                    float2 r0 = *(const float2*)(res + off0);
                    float2 r1 = *(const float2*)(res + off1);
                    o0.x += r0.x; o0.y += r0.y;
                    o1.x += r1.x; o1.y += r1.y;
                }
                *(float2*)(C + off0) = o0;
                *(float2*)(C + off1) = o1;
            }
        }
    }
}

// ---------------------------------------------------------------------------
// Fused flash attention (bf16 HMMA, hi/lo 3-term). Output bf16 hi/lo.
// Grid: (TQ/128 = 8, BH = 64), 256 threads (8 warps, 16 q-rows each).
// ---------------------------------------------------------------------------
#define FA_KBUF(buf) (32768 + (buf) * 32768)
#define FA_SMEM      (98304 + 512)

__global__ void __launch_bounds__(256, 1)
flash_kernel(const __nv_bfloat16* __restrict__ Qhi, const __nv_bfloat16* __restrict__ Qlo,
             const __nv_bfloat16* __restrict__ Khi, const __nv_bfloat16* __restrict__ Klo,
             const __nv_bfloat16* __restrict__ Vhi, const __nv_bfloat16* __restrict__ Vlo,
             const int* __restrict__ mask,
             __nv_bfloat16* __restrict__ Ohi, __nv_bfloat16* __restrict__ Olo) {
    extern __shared__ char smem[];
    uint32_t sb = smem_u32(smem);
    int tid = threadIdx.x;
    int lane = tid & 31, wid = tid >> 5;
    int qtile = blockIdx.x;
    int bh = blockIdx.y;
    int b = bh >> 4, h = bh & 15;

    size_t qrow0 = (size_t)b * TQ + (size_t)qtile * 128;
    size_t krow0 = (size_t)b * TK;
    uint32_t hbyte = (uint32_t)h * 128;

    uint32_t sQh = sb, sQl = sb + 16384;
    float* mfbase = (float*)(smem + 98304);

    {
        const char* gh = (const char*)Qhi;
        const char* gl = (const char*)Qlo;
        #pragma unroll
        for (int it = 0; it < 4; it++) {
            int idx = tid + it * 256;
            int r = idx >> 3, c16 = (idx & 7) * 16;
            uint32_t so = (uint32_t)(r * 128 + c16);
            uint32_t sw = so ^ ((so >> 3) & 0x70);
            size_t go = (qrow0 + r) * 2048 + hbyte + c16;
            cpasync16(sQh + sw, gh + go);
            cpasync16(sQl + sw, gl + go);
        }
    }

    const char* gK[2] = {(const char*)Khi, (const char*)Klo};
    const char* gV[2] = {(const char*)Vhi, (const char*)Vlo};

    {
        uint32_t base = sb + FA_KBUF(0);
        #pragma unroll
        for (int t = 0; t < 4; t++) {
            const char* src = (t < 2) ? gK[t] : gV[t - 2];
            uint32_t tb = base + t * 8192;
            #pragma unroll
            for (int it = 0; it < 2; it++) {
                int idx = tid + it * 256;
                int r = idx >> 3, c16 = (idx & 7) * 16;
                uint32_t so = (uint32_t)(r * 128 + c16);
                uint32_t sw = so ^ ((so >> 3) & 0x70);
                cpasync16(tb + sw, src + (krow0 + r) * 2048 + hbyte + c16);
            }
        }
    }
    CP_COMMIT();
    if (tid < 64) mfbase[tid] = mask[(size_t)b * TK + tid] ? 1.f : 0.f;
    {
        uint32_t base = sb + FA_KBUF(1);
        #pragma unroll
        for (int t = 0; t < 4; t++) {
            const char* src = (t < 2) ? gK[t] : gV[t - 2];
            uint32_t tb = base + t * 8192;
            #pragma unroll
            for (int it = 0; it < 2; it++) {
                int idx = tid + it * 256;
                int r = idx >> 3, c16 = (idx & 7) * 16;
                uint32_t so = (uint32_t)(r * 128 + c16);
                uint32_t sw = so ^ ((so >> 3) & 0x70);
                cpasync16(tb + sw, src + (krow0 + 64 + r) * 2048 + hbyte + c16);
            }
        }
    }
    CP_COMMIT();
    if (tid < 64) mfbase[64 + tid] = mask[(size_t)b * TK + 64 + tid] ? 1.f : 0.f;

    uint32_t xorb = (uint32_t)((lane & 7) * 16);
    uint32_t aHi  = (uint32_t)(((lane >> 4) & 1) * 16);
    uint32_t kRowBase = 8 * ((lane >> 4) & 1) + (lane & 7);
    uint32_t kColHalf = 16 * ((lane >> 3) & 1);
    uint32_t vRowBase = 8 * ((lane >> 3) & 1) + (lane & 7);
    uint32_t vColHalf = 16 * ((lane >> 4) & 1);

    float O[8][4];
    #pragma unroll
    for (int f = 0; f < 8; f++)
        #pragma unroll
        for (int r = 0; r < 4; r++) O[f][r] = 0.f;
    float mrow0 = -INFINITY, mrow1 = -INFINITY;
    float lrow0 = 0.f, lrow1 = 0.f;
    uint32_t QhF[4][4], QlF[4][4];

    #pragma unroll 1
    for (int c = 0; c < 16; c++) {
        int buf = c & 1;
        if (c < 15) { CP_WAIT(1); } else { CP_WAIT(0); }
        __syncthreads();

        if (c == 0) {
            #pragma unroll
            for (int ks = 0; ks < 4; ks++) {
                uint32_t row = (uint32_t)(wid * 16 + (lane & 15));
                uint32_t col = ((uint32_t)(ks * 32) + aHi) ^ xorb;
                ldm4(QhF[ks], sQh + row * 128 + col);
                ldm4(QlF[ks], sQl + row * 128 + col);
            }
        }

        uint32_t sKh = sb + FA_KBUF(buf);
        uint32_t sKl = sKh + 8192;
        uint32_t sVh = sKh + 16384;
        uint32_t sVl = sKh + 24576;
        const float* mf = mfbase + buf * 64;

        float S[8][4];
        #pragma unroll
        for (int n = 0; n < 8; n++)
            #pragma unroll
            for (int r = 0; r < 4; r++) S[n][r] = 0.f;

        #pragma unroll
        for (int ks = 0; ks < 4; ks++) {
            uint32_t col = ((uint32_t)(ks * 32) + kColHalf) ^ xorb;
            #pragma unroll
            for (int np = 0; np < 4; np++) {
                uint32_t KhF[4], KlF[4];
                uint32_t ro = (np * 16 + kRowBase) * 128;
                ldm4(KhF, sKh + ro + col);
                ldm4(KlF, sKl + ro + col);
                mma16816(S[np*2],   QhF[ks], KhF);
                mma16816(S[np*2],   QhF[ks], KlF);
                mma16816(S[np*2],   QlF[ks], KhF);
                mma16816(S[np*2+1], QhF[ks], KhF + 2);
                mma16816(S[np*2+1], QhF[ks], KlF + 2);
                mma16816(S[np*2+1], QlF[ks], KhF + 2);
            }
        }

        #pragma unroll
        for (int n = 0; n < 8; n++) {
            int j = 8 * n + (lane & 3) * 2;
            float mk0 = mf[j], mk1 = mf[j + 1];
            S[n][0] = (mk0 != 0.f) ? S[n][0] * 0.125f : -1e30f;
            S[n][1] = (mk1 != 0.f) ? S[n][1] * 0.125f : -1e30f;
            S[n][2] = (mk0 != 0.f) ? S[n][2] * 0.125f : -1e30f;
            S[n][3] = (mk1 != 0.f) ? S[n][3] * 0.125f : -1e30f;
        }

        float cm0 = -INFINITY, cm1 = -INFINITY;
        #pragma unroll
        for (int n = 0; n < 8; n++) {
            cm0 = fmaxf(cm0, fmaxf(S[n][0], S[n][1]));
            cm1 = fmaxf(cm1, fmaxf(S[n][2], S[n][3]));
        }
        cm0 = fmaxf(cm0, __shfl_xor_sync(0xffffffffu, cm0, 1));
        cm0 = fmaxf(cm0, __shfl_xor_sync(0xffffffffu, cm0, 2));
        cm1 = fmaxf(cm1, __shfl_xor_sync(0xffffffffu, cm1, 1));
        cm1 = fmaxf(cm1, __shfl_xor_sync(0xffffffffu, cm1, 2));

        float mn0 = fmaxf(mrow0, cm0);
        float mn1 = fmaxf(mrow1, cm1);
        float al0 = __expf(mrow0 - mn0);
        float al1 = __expf(mrow1 - mn1);
        mrow0 = mn0; mrow1 = mn1;

        uint32_t Phi[4][4], Plo[4][4];
        float sum0 = 0.f, sum1 = 0.f;
        #pragma unroll
        for (int n = 0; n < 8; n++) {
            float p0 = __expf(S[n][0] - mn0);
            float p1 = __expf(S[n][1] - mn0);
            float p2 = __expf(S[n][2] - mn1);
            float p3 = __expf(S[n][3] - mn1);
            sum0 += p0 + p1;
            sum1 += p2 + p3;
            __nv_bfloat162 h01 = __floats2bfloat162_rn(p0, p1);
            __nv_bfloat162 h23 = __floats2bfloat162_rn(p2, p3);
            __nv_bfloat162 l01 = __floats2bfloat162_rn(
                p0 - __bfloat162float(h01.x), p1 - __bfloat162float(h01.y));
            __nv_bfloat162 l23 = __floats2bfloat162_rn(
                p2 - __bfloat162float(h23.x), p3 - __bfloat162float(h23.y));
            int kk = n >> 1, base = (n & 1) * 2;
            Phi[kk][base]     = *(uint32_t*)&h01;
            Phi[kk][base + 1] = *(uint32_t*)&h23;
            Plo[kk][base]     = *(uint32_t*)&l01;
            Plo[kk][base + 1] = *(uint32_t*)&l23;
        }
        sum0 += __shfl_xor_sync(0xffffffffu, sum0, 1);
        sum0 += __shfl_xor_sync(0xffffffffu, sum0, 2);
        sum1 += __shfl_xor_sync(0xffffffffu, sum1, 1);
        sum1 += __shfl_xor_sync(0xffffffffu, sum1, 2);
        lrow0 = lrow0 * al0 + sum0;
        lrow1 = lrow1 * al1 + sum1;
        #pragma unroll
        for (int f = 0; f < 8; f++) {
            O[f][0] *= al0; O[f][1] *= al0;
            O[f][2] *= al1; O[f][3] *= al1;
        }

        #pragma unroll
        for (int ks = 0; ks < 4; ks++) {
            uint32_t ro = (ks * 16 + vRowBase) * 128;
            #pragma unroll
            for (int dp = 0; dp < 4; dp++) {
                uint32_t col = ((uint32_t)(dp * 32) + vColHalf) ^ xorb;
                uint32_t VhF[4], VlF[4];
                ldm4t(VhF, sVh + ro + col);
                ldm4t(VlF, sVl + ro + col);
                mma16816(O[dp*2],   Phi[ks], VhF);
                mma16816(O[dp*2],   Phi[ks], VlF);
                mma16816(O[dp*2],   Plo[ks], VhF);
                mma16816(O[dp*2+1], Phi[ks], VhF + 2);
                mma16816(O[dp*2+1], Phi[ks], VlF + 2);
                mma16816(O[dp*2+1], Plo[ks], VhF + 2);
            }
        }

        __syncthreads();
        if (c < 14) {
            int T0 = (c + 2) * 64;
            uint32_t base = sb + FA_KBUF(buf);
            #pragma unroll
            for (int t = 0; t < 4; t++) {
                const char* src = (t < 2) ? gK[t] : gV[t - 2];
                uint32_t tb = base + t * 8192;
                #pragma unroll
                for (int it = 0; it < 2; it++) {
                    int idx = tid + it * 256;
                    int r = idx >> 3, c16 = (idx & 7) * 16;
                    uint32_t so = (uint32_t)(r * 128 + c16);
                    uint32_t sw = so ^ ((so >> 3) & 0x70);
                    cpasync16(tb + sw, src + (krow0 + T0 + r) * 2048 + hbyte + c16);
                }
            }
            CP_COMMIT();
            if (tid < 64)
                mfbase[buf * 64 + tid] = mask[(size_t)b * TK + T0 + tid] ? 1.f : 0.f;
        }
    }

    float rinv0 = 1.f / lrow0;
    float rinv1 = 1.f / lrow1;
    int grow = (int)qrow0 + wid * 16 + (lane >> 2);
    int col0 = h * 64 + (lane & 3) * 2;
    #pragma unroll
    for (int f = 0; f < 8; f++) {
        int cc = col0 + 8 * f;
        float v0 = O[f][0] * rinv0, v1 = O[f][1] * rinv0;
        float v2 = O[f][2] * rinv1, v3 = O[f][3] * rinv1;
        __nv_bfloat162 h0 = __floats2bfloat162_rn(v0, v1);
        __nv_bfloat162 h1 = __floats2bfloat162_rn(v2, v3);
        __nv_bfloat162 l0 = __floats2bfloat162_rn(v0 - __bfloat162float(h0.x),
                                                  v1 - __bfloat162float(h0.y));
        __nv_bfloat162 l1 = __floats2bfloat162_rn(v2 - __bfloat162float(h1.x),
                                                  v3 - __bfloat162float(h1.y));
        size_t off0 = (size_t)grow * DD + cc;
        size_t off1 = (size_t)(grow + 8) * DD + cc;
        *(__nv_bfloat162*)(Ohi + off0) = h0;
        *(__nv_bfloat162*)(Ohi + off1) = h1;
        *(__nv_bfloat162*)(Olo + off0) = l0;
        *(__nv_bfloat162*)(Olo + off1) = l1;
    }
}

// ---------------------------------------------------------------------------
// Launch
// ---------------------------------------------------------------------------
extern "C" void kernel_launch(void* const* d_in, const int* in_sizes, int n_in,
                              void* d_out, int out_size) {
    const float* x      = (const float*)d_in[0];
    const float* y      = (const float*)d_in[1];
    const int*   mask   = (const int*)d_in[2];
    const float* ln1_g  = (const float*)d_in[3];
    const float* ln1_b  = (const float*)d_in[4];
    const float* ln2_g  = (const float*)d_in[5];
    const float* ln2_b  = (const float*)d_in[6];
    const float* q_w    = (const float*)d_in[7];
    const float* q_b    = (const float*)d_in[8];
    const float* k_w    = (const float*)d_in[9];
    const float* k_b    = (const float*)d_in[10];
    const float* v_w    = (const float*)d_in[11];
    const float* v_b    = (const float*)d_in[12];
    const float* o_w    = (const float*)d_in[13];
    const float* o_b    = (const float*)d_in[14];
    const float* mln1_g = (const float*)d_in[15];
    const float* mln1_b = (const float*)d_in[16];
    const float* l1_w   = (const float*)d_in[17];
    const float* l1_b   = (const float*)d_in[18];
    const float* mln2_g = (const float*)d_in[19];
    const float* mln2_b = (const float*)d_in[20];
    const float* l2_w   = (const float*)d_in[21];
    const float* l2_b   = (const float*)d_in[22];
    float* out = (float*)d_out;

    float *x2, *hbuf;
    __nv_bfloat16 *xhi, *xlo, *yhi, *ylo, *phi, *plo, *bhi, *blo;
    __nv_bfloat16 *qhi, *qlo, *khi, *klo, *vhi, *vlo;
    cudaGetSymbolAddress((void**)&x2,   g_x2);
    cudaGetSymbolAddress((void**)&hbuf, g_h);
    cudaGetSymbolAddress((void**)&xhi,  g_xhi);
    cudaGetSymbolAddress((void**)&xlo,  g_xlo);
    cudaGetSymbolAddress((void**)&yhi,  g_yhi);
    cudaGetSymbolAddress((void**)&ylo,  g_ylo);
    cudaGetSymbolAddress((void**)&phi,  g_phi);
    cudaGetSymbolAddress((void**)&plo,  g_plo);
    cudaGetSymbolAddress((void**)&bhi,  g_bhi);
    cudaGetSymbolAddress((void**)&blo,  g_blo);
    cudaGetSymbolAddress((void**)&qhi,  g_qhi);
    cudaGetSymbolAddress((void**)&qlo,  g_qlo);
    cudaGetSymbolAddress((void**)&khi,  g_khi);
    cudaGetSymbolAddress((void**)&klo,  g_klo);
    cudaGetSymbolAddress((void**)&vhi,  g_vhi);
    cudaGetSymbolAddress((void**)&vlo,  g_vlo);

    cudaFuncSetAttribute(gemm_hmma, cudaFuncAttributeMaxDynamicSharedMemorySize, GT_SMEM);
    cudaFuncSetAttribute(flash_kernel, cudaFuncAttributeMaxDynamicSharedMemorySize, FA_SMEM);

    dim3 gemmGrid(8, 16);                       // N/128, M/256 = 128 CTAs
    dim3 tGrid(32, 32);
    dim3 tBlock(32, 8);

    // 1) pre-norms -> bf16 hi/lo directly
    ln_relu_split_kernel<<<MROWS, 256>>>(x, ln1_g, ln1_b, xhi, xlo);
    ln_relu_split_kernel<<<BB * TK, 256>>>(y, ln2_g, ln2_b, yhi, ylo);

    // 2) q/k/v projections -> bf16 hi/lo directly
    transpose_split_kernel<<<tGrid, tBlock>>>(q_w, bhi, blo);
    gemm_hmma<<<gemmGrid, GT_THREADS, GT_SMEM>>>(xhi, xlo, bhi, blo, q_b, nullptr,
                                                 nullptr, qhi, qlo);
    transpose_split_kernel<<<tGrid, tBlock>>>(k_w, bhi, blo);
    gemm_hmma<<<gemmGrid, GT_THREADS, GT_SMEM>>>(yhi, ylo, bhi, blo, k_b, nullptr,
                                                 nullptr, khi, klo);
    transpose_split_kernel<<<tGrid, tBlock>>>(v_w, bhi, blo);
    gemm_hmma<<<gemmGrid, GT_THREADS, GT_SMEM>>>(yhi, ylo, bhi, blo, v_b, nullptr,
                                                 nullptr, vhi, vlo);

    // 3) fused flash attention -> bf16 hi/lo
    flash_kernel<<<dim3(8, BH), 256, FA_SMEM>>>(qhi, qlo, khi, klo, vhi, vlo,
                                                mask, phi, plo);

    // 4) output proj + residual (fp32 out)
    transpose_split_kernel<<<tGrid, tBlock>>>(o_w, bhi, blo);
    gemm_hmma<<<gemmGrid, GT_THREADS, GT_SMEM>>>(phi, plo, bhi, blo, o_b, x,
                                                 x2, nullptr, nullptr);

    // 5) MLP
    ln_relu_split_kernel<<<MROWS, 256>>>(x2, mln1_g, mln1_b, xhi, xlo);
    transpose_split_kernel<<<tGrid, tBlock>>>(l1_w, bhi, blo);
    gemm_hmma<<<gemmGrid, GT_THREADS, GT_SMEM>>>(xhi, xlo, bhi, blo, l1_b, nullptr,
                                                 hbuf, nullptr, nullptr);

    ln_relu_split_kernel<<<MROWS, 256>>>(hbuf, mln2_g, mln2_b, yhi, ylo);
    transpose_split_kernel<<<tGrid, tBlock>>>(l2_w, bhi, blo);
    gemm_hmma<<<gemmGrid, GT_THREADS, GT_SMEM>>>(yhi, ylo, bhi, blo, l2_b, nullptr,
                                                 out, nullptr, nullptr);
}

// round 8
// speedup vs baseline: 1.5531x; 1.5531x over previous
#include <cuda_runtime.h>
#include <cuda_fp16.h>
#include <math.h>
#include <stdint.h>

// ---------------------------------------------------------------------------
// Problem dims (fixed)
// ---------------------------------------------------------------------------
#define BB 4
#define TQ 1024
#define TK 1024
#define DD 1024
#define HH 16
#define DK 64
#define DV 64
#define MROWS (BB * TQ)          // 4096
#define BH (BB * HH)             // 64

// ---------------------------------------------------------------------------
// Scratch (device globals — no allocations allowed)
// ---------------------------------------------------------------------------
__device__ float g_x2 [MROWS * DD];
__device__ float g_h  [MROWS * DD];
// fp16 activation buffers (single precision path; error budget analysis in header)
__device__ __half g_xh[MROWS * DD];    // ln1(x) / mln1(x2) reuse
__device__ __half g_yh[MROWS * DD];    // ln2(y) / mln2(h) reuse
__device__ __half g_ph[MROWS * DD];    // flash output
// weight (transposed) hi/lo fp16
__device__ __half g_bhi[DD * DD];
__device__ __half g_blo[DD * DD];
// q/k/v fp16 (written directly by GEMM epilogue)
__device__ __half g_qh[MROWS * DD];
__device__ __half g_kh[MROWS * DD];
__device__ __half g_vh[MROWS * DD];

// ---------------------------------------------------------------------------
// PTX helpers (sm_80+ baseline features only)
// ---------------------------------------------------------------------------
__device__ __forceinline__ uint32_t smem_u32(const void* p) {
    uint32_t a;
    asm("{ .reg .u64 t; cvta.to.shared.u64 t, %1; cvt.u32.u64 %0, t; }" : "=r"(a) : "l"(p));
    return a;
}
__device__ __forceinline__ void cpasync16(uint32_t dst, const void* src) {
    asm volatile("cp.async.cg.shared.global [%0], [%1], 16;" :: "r"(dst), "l"(src) : "memory");
}
#define CP_COMMIT() asm volatile("cp.async.commit_group;" ::: "memory")
#define CP_WAIT(n)  asm volatile("cp.async.wait_group %0;" :: "n"(n) : "memory")

__device__ __forceinline__ void ldm4(uint32_t* r, uint32_t addr) {
    asm volatile("ldmatrix.sync.aligned.m8n8.x4.shared.b16 {%0,%1,%2,%3}, [%4];"
        : "=r"(r[0]), "=r"(r[1]), "=r"(r[2]), "=r"(r[3]) : "r"(addr));
}
__device__ __forceinline__ void ldm4t(uint32_t* r, uint32_t addr) {
    asm volatile("ldmatrix.sync.aligned.m8n8.x4.trans.shared.b16 {%0,%1,%2,%3}, [%4];"
        : "=r"(r[0]), "=r"(r[1]), "=r"(r[2]), "=r"(r[3]) : "r"(addr));
}
// fp16 mma, fp32 accumulate
__device__ __forceinline__ void mma16816h(float* d, const uint32_t* a, const uint32_t* b) {
    asm volatile("mma.sync.aligned.m16n8k16.row.col.f32.f16.f16.f32 "
        "{%0,%1,%2,%3}, {%4,%5,%6,%7}, {%8,%9}, {%0,%1,%2,%3};"
        : "+f"(d[0]), "+f"(d[1]), "+f"(d[2]), "+f"(d[3])
        : "r"(a[0]), "r"(a[1]), "r"(a[2]), "r"(a[3]), "r"(b[0]), "r"(b[1]));
}

// ---------------------------------------------------------------------------
// LayerNorm + ReLU -> single fp16
// ---------------------------------------------------------------------------
__global__ void ln_relu_h_kernel(const float* __restrict__ in,
                                 const float* __restrict__ gamma,
                                 const float* __restrict__ beta,
                                 __half* __restrict__ out) {
    int row = blockIdx.x;
    int tid = threadIdx.x;
    const float* p = in + (size_t)row * DD + tid * 4;
    float4 xv = *(const float4*)p;

    float s  = xv.x + xv.y + xv.z + xv.w;
    float ss = xv.x*xv.x + xv.y*xv.y + xv.z*xv.z + xv.w*xv.w;
    #pragma unroll
    for (int off = 16; off > 0; off >>= 1) {
        s  += __shfl_xor_sync(0xffffffffu, s,  off);
        ss += __shfl_xor_sync(0xffffffffu, ss, off);
    }
    __shared__ float sbuf[8], ssbuf[8];
    __shared__ float smean, sinv;
    int lane = tid & 31, warp = tid >> 5;
    if (lane == 0) { sbuf[warp] = s; ssbuf[warp] = ss; }
    __syncthreads();
    if (tid == 0) {
        float ts = 0.f, tss = 0.f;
        #pragma unroll
        for (int i = 0; i < 8; i++) { ts += sbuf[i]; tss += ssbuf[i]; }
        float mean = ts * (1.0f / DD);
        float var  = tss * (1.0f / DD) - mean * mean;
        smean = mean;
        sinv  = rsqrtf(var + 1e-5f);
    }
    __syncthreads();
    float m = smean, inv = sinv;

    int c = tid * 4;
    float4 g4 = *(const float4*)(gamma + c);
    float4 b4 = *(const float4*)(beta  + c);
    float o0 = fmaxf(0.f, (xv.x - m) * inv * g4.x + b4.x);
    float o1 = fmaxf(0.f, (xv.y - m) * inv * g4.y + b4.y);
    float o2 = fmaxf(0.f, (xv.z - m) * inv * g4.z + b4.z);
    float o3 = fmaxf(0.f, (xv.w - m) * inv * g4.w + b4.w);

    size_t base = (size_t)row * DD + c;
    *(__half2*)(out + base)     = __floats2half2_rn(o0, o1);
    *(__half2*)(out + base + 2) = __floats2half2_rn(o2, o3);
}

// ---------------------------------------------------------------------------
// Transpose + split: W[K,N] fp32 -> Wt_hi/Wt_lo [N,K] fp16 (lo may be subnormal)
// ---------------------------------------------------------------------------
__global__ void transpose_split_kernel(const float* __restrict__ W,
                                       __half* __restrict__ hi,
                                       __half* __restrict__ lo) {
    __shared__ float tile[32][33];
    int tx = threadIdx.x, ty = threadIdx.y;          // 32 x 8
    int n0 = blockIdx.x * 32, k0 = blockIdx.y * 32;
    #pragma unroll
    for (int i = 0; i < 4; i++) {
        int kr = ty + i * 8;
        tile[kr][tx] = W[(size_t)(k0 + kr) * DD + n0 + tx];
    }
    __syncthreads();
    #pragma unroll
    for (int i = 0; i < 4; i++) {
        int nr = ty + i * 8;
        float v = tile[tx][nr];
        __half h = __float2half_rn(v);
        __half l = __float2half_rn(v - __half2float(h));
        hi[(size_t)(n0 + nr) * DD + k0 + tx] = h;
        lo[(size_t)(n0 + nr) * DD + k0 + tx] = l;
    }
}

// ---------------------------------------------------------------------------
// HMMA GEMM (fp16, 2-term): C = A @ (Bh + Bl)^T (+bias, +res)
// A: single fp16 [M,K]; B: hi/lo fp16 [N,K].
// CTA 256x128, BK=64, double-buffered cp.async, 16 warps (4M x 4N), wtile 64x32.
// smem: A[2]=64K  Bh[2]=32K  Bl[2]=32K -> 128K.  Grid (8,16) = 128 CTAs.
// ---------------------------------------------------------------------------
#define GA_OFF(buf)  ((buf) * 32768)
#define GB_OFF(buf)  (65536 + (buf) * 16384)
#define GBL_OFF(buf) (98304 + (buf) * 16384)
#define GT_SMEM 131072
#define GT_THREADS 512

struct GPtrs { const char *a, *bhi, *blo; };

__device__ __forceinline__ void gt_load_chunk(uint32_t sb, int buf,
                                              const GPtrs& g, int chunk, int tid) {
    size_t kbyte = (size_t)chunk * 128;
    // A tile: 256 rows x 128B = 2048 x 16B
    {
        uint32_t base = sb + GA_OFF(buf);
        #pragma unroll
        for (int it = 0; it < 4; it++) {
            int idx = tid + it * GT_THREADS;        // 0..2047
            int r = idx >> 3;
            int c16 = idx & 7;
            uint32_t so = (uint32_t)(r * 128 + c16 * 16);
            uint32_t sw = so ^ ((so >> 3) & 0x70);
            cpasync16(base + sw, g.a + (size_t)r * 2048 + kbyte + c16 * 16);
        }
    }
    // B tiles: 128 rows x 128B = 1024 x 16B each (hi, lo)
    #pragma unroll
    for (int t = 0; t < 2; t++) {
        uint32_t base = sb + (t ? GBL_OFF(buf) : GB_OFF(buf));
        const char* src = t ? g.blo : g.bhi;
        #pragma unroll
        for (int it = 0; it < 2; it++) {
            int idx = tid + it * GT_THREADS;        // 0..1023
            int r = idx >> 3;
            int c16 = idx & 7;
            uint32_t so = (uint32_t)(r * 128 + c16 * 16);
            uint32_t sw = so ^ ((so >> 3) & 0x70);
            cpasync16(base + sw, src + (size_t)r * 2048 + kbyte + c16 * 16);
        }
    }
}

__global__ void __launch_bounds__(GT_THREADS, 1)
gemm_hmma(const __half* __restrict__ A,
          const __half* __restrict__ Bhi, const __half* __restrict__ Blo,
          const float* __restrict__ bias, const float* __restrict__ res,
          float* __restrict__ C, __half* __restrict__ Ch) {
    extern __shared__ char smem[];
    uint32_t sb = smem_u32(smem);
    int tid = threadIdx.x;
    int lane = tid & 31;
    int wid = tid >> 5;              // 0..15
    int wm = wid & 3;                // 0..3 (M, 64 rows each)
    int wn = wid >> 2;               // 0..3 (N, 32 cols each)

    int n0 = blockIdx.x * 128;
    int m0 = blockIdx.y * 256;

    GPtrs g;
    g.a   = (const char*)(A   + (size_t)m0 * DD);
    g.bhi = (const char*)(Bhi + (size_t)n0 * DD);
    g.blo = (const char*)(Blo + (size_t)n0 * DD);

    float acc[4][4][4];
    #pragma unroll
    for (int i = 0; i < 4; i++)
        #pragma unroll
        for (int j = 0; j < 4; j++)
            #pragma unroll
            for (int r = 0; r < 4; r++) acc[i][j][r] = 0.f;

    uint32_t aRow = (uint32_t)(wm * 64 + (lane & 15));
    uint32_t xorb = (uint32_t)((lane & 7) * 16);
    uint32_t aHi  = (uint32_t)(((lane >> 4) & 1) * 16);
    uint32_t bRow = (uint32_t)(wn * 32 + ((lane >> 4) & 1) * 8 + (lane & 7));
    uint32_t bHi  = (uint32_t)(((lane >> 3) & 1) * 16);

    gt_load_chunk(sb, 0, g, 0, tid);
    CP_COMMIT();

    #pragma unroll 1
    for (int c = 0; c < 16; c++) {
        int buf = c & 1;
        if (c < 15) {
            gt_load_chunk(sb, buf ^ 1, g, c + 1, tid);
            CP_COMMIT();
            CP_WAIT(1);
        } else {
            CP_WAIT(0);
        }
        __syncthreads();

        uint32_t tA  = sb + GA_OFF(buf);
        uint32_t tBh = sb + GB_OFF(buf);
        uint32_t tBl = sb + GBL_OFF(buf);

        #pragma unroll
        for (int ks = 0; ks < 4; ks++) {
            uint32_t ka = ((uint32_t)(ks * 32) + aHi) ^ xorb;
            uint32_t kb = ((uint32_t)(ks * 32) + bHi) ^ xorb;

            uint32_t Af[4][4], Bh[2][4], Bl[2][4];
            #pragma unroll
            for (int i = 0; i < 4; i++) {
                uint32_t ro = (aRow + 16 * i) * 128;
                ldm4(Af[i], tA + ro + ka);
            }
            #pragma unroll
            for (int jp = 0; jp < 2; jp++) {
                uint32_t ro = (bRow + 16 * jp) * 128;
                ldm4(Bh[jp], tBh + ro + kb);
                ldm4(Bl[jp], tBl + ro + kb);
            }
            #pragma unroll
            for (int i = 0; i < 4; i++) {
                #pragma unroll
                for (int j = 0; j < 4; j++) {
                    const uint32_t* bh = &Bh[j >> 1][(j & 1) * 2];
                    const uint32_t* bl = &Bl[j >> 1][(j & 1) * 2];
                    mma16816h(acc[i][j], Af[i], bh);
                    mma16816h(acc[i][j], Af[i], bl);
                }
            }
        }
        __syncthreads();
    }

    int rbase = m0 + wm * 64 + (lane >> 2);
    int cbase = n0 + wn * 32 + (lane & 3) * 2;
    #pragma unroll
    for (int j = 0; j < 4; j++) {
        int cc = cbase + 8 * j;
        float2 b2 = *(const float2*)(bias + cc);
        #pragma unroll
        for (int i = 0; i < 4; i++) {
            int r = rbase + 16 * i;
            float2 o0 = {acc[i][j][0] + b2.x, acc[i][j][1] + b2.y};
            float2 o1 = {acc[i][j][2] + b2.x, acc[i][j][3] + b2.y};
            size_t off0 = (size_t)r * DD + cc;
            size_t off1 = (size_t)(r + 8) * DD + cc;
            if (Ch) {
                *(__half2*)(Ch + off0) = __floats2half2_rn(o0.x, o0.y);
                *(__half2*)(Ch + off1) = __floats2half2_rn(o1.x, o1.y);
            } else {
                if (res) {
                    float2 r0 = *(const float2*)(res + off0);
                    float2 r1 = *(const float2*)(res + off1);
                    o0.x += r0.x; o0.y += r0.y;
                    o1.x += r1.x; o1.y += r1.y;
                }
                *(float2*)(C + off0) = o0;
                *(float2*)(C + off1) = o1;
            }
        }
    }
}

// ---------------------------------------------------------------------------
// Fused flash attention (single fp16 HMMA). Output single fp16.
// Grid: (TQ/128 = 8, BH = 64), 256 threads (8 warps, 16 q-rows each).
// smem: Q 16K | 2 x [K 8K, V 8K] | mask 512B  -> ~49.7K; 2 CTAs/SM.
// ---------------------------------------------------------------------------
#define FA_KBUF(buf) (16384 + (buf) * 16384)
#define FA_SMEM      (49152 + 512)

__global__ void __launch_bounds__(256, 2)
flash_kernel(const __half* __restrict__ Qh, const __half* __restrict__ Kh,
             const __half* __restrict__ Vh, const int* __restrict__ mask,
             __half* __restrict__ Oh) {
    extern __shared__ char smem[];
    uint32_t sb = smem_u32(smem);
    int tid = threadIdx.x;
    int lane = tid & 31, wid = tid >> 5;
    int qtile = blockIdx.x;
    int bh = blockIdx.y;
    int b = bh >> 4, h = bh & 15;

    size_t qrow0 = (size_t)b * TQ + (size_t)qtile * 128;
    size_t krow0 = (size_t)b * TK;
    uint32_t hbyte = (uint32_t)h * 128;

    uint32_t sQ = sb;
    float* mfbase = (float*)(smem + 49152);

    // Q tile: 128 rows x 128B = 1024 x 16B
    {
        const char* gq = (const char*)Qh;
        #pragma unroll
        for (int it = 0; it < 4; it++) {
            int idx = tid + it * 256;
            int r = idx >> 3, c16 = (idx & 7) * 16;
            uint32_t so = (uint32_t)(r * 128 + c16);
            uint32_t sw = so ^ ((so >> 3) & 0x70);
            cpasync16(sQ + sw, gq + (qrow0 + r) * 2048 + hbyte + c16);
        }
    }

    const char* gK = (const char*)Kh;
    const char* gV = (const char*)Vh;

    #pragma unroll
    for (int pre = 0; pre < 2; pre++) {
        uint32_t base = sb + FA_KBUF(pre);
        #pragma unroll
        for (int t = 0; t < 2; t++) {
            const char* src = t ? gV : gK;
            uint32_t tb = base + t * 8192;
            #pragma unroll
            for (int it = 0; it < 2; it++) {
                int idx = tid + it * 256;
                int r = idx >> 3, c16 = (idx & 7) * 16;
                uint32_t so = (uint32_t)(r * 128 + c16);
                uint32_t sw = so ^ ((so >> 3) & 0x70);
                cpasync16(tb + sw, src + (krow0 + pre * 64 + r) * 2048 + hbyte + c16);
            }
        }
        CP_COMMIT();
        if (tid < 64)
            mfbase[pre * 64 + tid] = mask[(size_t)b * TK + pre * 64 + tid] ? 1.f : 0.f;
    }

    uint32_t xorb = (uint32_t)((lane & 7) * 16);
    uint32_t aHi  = (uint32_t)(((lane >> 4) & 1) * 16);
    uint32_t kRowBase = 8 * ((lane >> 4) & 1) + (lane & 7);
    uint32_t kColHalf = 16 * ((lane >> 3) & 1);
    uint32_t vRowBase = 8 * ((lane >> 3) & 1) + (lane & 7);
    uint32_t vColHalf = 16 * ((lane >> 4) & 1);

    float O[8][4];
    #pragma unroll
    for (int f = 0; f < 8; f++)
        #pragma unroll
        for (int r = 0; r < 4; r++) O[f][r] = 0.f;
    float mrow0 = -INFINITY, mrow1 = -INFINITY;
    float lrow0 = 0.f, lrow1 = 0.f;
    uint32_t QF[4][4];

    #pragma unroll 1
    for (int c = 0; c < 16; c++) {
        int buf = c & 1;
        if (c < 15) { CP_WAIT(1); } else { CP_WAIT(0); }
        __syncthreads();

        if (c == 0) {
            #pragma unroll
            for (int ks = 0; ks < 4; ks++) {
                uint32_t row = (uint32_t)(wid * 16 + (lane & 15));
                uint32_t col = ((uint32_t)(ks * 32) + aHi) ^ xorb;
                ldm4(QF[ks], sQ + row * 128 + col);
            }
        }

        uint32_t sK = sb + FA_KBUF(buf);
        uint32_t sV = sK + 8192;
        const float* mf = mfbase + buf * 64;

        float S[8][4];
        #pragma unroll
        for (int n = 0; n < 8; n++)
            #pragma unroll
            for (int r = 0; r < 4; r++) S[n][r] = 0.f;

        #pragma unroll
        for (int ks = 0; ks < 4; ks++) {
            uint32_t col = ((uint32_t)(ks * 32) + kColHalf) ^ xorb;
            #pragma unroll
            for (int np = 0; np < 4; np++) {
                uint32_t KF[4];
                uint32_t ro = (np * 16 + kRowBase) * 128;
                ldm4(KF, sK + ro + col);
                mma16816h(S[np*2],   QF[ks], KF);
                mma16816h(S[np*2+1], QF[ks], KF + 2);
            }
        }

        #pragma unroll
        for (int n = 0; n < 8; n++) {
            int j = 8 * n + (lane & 3) * 2;
            float mk0 = mf[j], mk1 = mf[j + 1];
            S[n][0] = (mk0 != 0.f) ? S[n][0] * 0.125f : -1e30f;
            S[n][1] = (mk1 != 0.f) ? S[n][1] * 0.125f : -1e30f;
            S[n][2] = (mk0 != 0.f) ? S[n][2] * 0.125f : -1e30f;
            S[n][3] = (mk1 != 0.f) ? S[n][3] * 0.125f : -1e30f;
        }

        float cm0 = -INFINITY, cm1 = -INFINITY;
        #pragma unroll
        for (int n = 0; n < 8; n++) {
            cm0 = fmaxf(cm0, fmaxf(S[n][0], S[n][1]));
            cm1 = fmaxf(cm1, fmaxf(S[n][2], S[n][3]));
        }
        cm0 = fmaxf(cm0, __shfl_xor_sync(0xffffffffu, cm0, 1));
        cm0 = fmaxf(cm0, __shfl_xor_sync(0xffffffffu, cm0, 2));
        cm1 = fmaxf(cm1, __shfl_xor_sync(0xffffffffu, cm1, 1));
        cm1 = fmaxf(cm1, __shfl_xor_sync(0xffffffffu, cm1, 2));

        float mn0 = fmaxf(mrow0, cm0);
        float mn1 = fmaxf(mrow1, cm1);
        float al0 = __expf(mrow0 - mn0);
        float al1 = __expf(mrow1 - mn1);
        mrow0 = mn0; mrow1 = mn1;

        uint32_t P[4][4];
        float sum0 = 0.f, sum1 = 0.f;
        #pragma unroll
        for (int n = 0; n < 8; n++) {
            float p0 = __expf(S[n][0] - mn0);
            float p1 = __expf(S[n][1] - mn0);
            float p2 = __expf(S[n][2] - mn1);
            float p3 = __expf(S[n][3] - mn1);
            sum0 += p0 + p1;
            sum1 += p2 + p3;
            __half2 h01 = __floats2half2_rn(p0, p1);
            __half2 h23 = __floats2half2_rn(p2, p3);
            int kk = n >> 1, base = (n & 1) * 2;
            P[kk][base]     = *(uint32_t*)&h01;
            P[kk][base + 1] = *(uint32_t*)&h23;
        }
        sum0 += __shfl_xor_sync(0xffffffffu, sum0, 1);
        sum0 += __shfl_xor_sync(0xffffffffu, sum0, 2);
        sum1 += __shfl_xor_sync(0xffffffffu, sum1, 1);
        sum1 += __shfl_xor_sync(0xffffffffu, sum1, 2);
        lrow0 = lrow0 * al0 + sum0;
        lrow1 = lrow1 * al1 + sum1;
        #pragma unroll
        for (int f = 0; f < 8; f++) {
            O[f][0] *= al0; O[f][1] *= al0;
            O[f][2] *= al1; O[f][3] *= al1;
        }

        #pragma unroll
        for (int ks = 0; ks < 4; ks++) {
            uint32_t ro = (ks * 16 + vRowBase) * 128;
            #pragma unroll
            for (int dp = 0; dp < 4; dp++) {
                uint32_t col = ((uint32_t)(dp * 32) + vColHalf) ^ xorb;
                uint32_t VF[4];
                ldm4t(VF, sV + ro + col);
                mma16816h(O[dp*2],   P[ks], VF);
                mma16816h(O[dp*2+1], P[ks], VF + 2);
            }
        }

        __syncthreads();
        if (c < 14) {
            int T0 = (c + 2) * 64;
            uint32_t base = sb + FA_KBUF(buf);
            #pragma unroll
            for (int t = 0; t < 2; t++) {
                const char* src = t ? gV : gK;
                uint32_t tb = base + t * 8192;
                #pragma unroll
                for (int it = 0; it < 2; it++) {
                    int idx = tid + it * 256;
                    int r = idx >> 3, c16 = (idx & 7) * 16;
                    uint32_t so = (uint32_t)(r * 128 + c16);
                    uint32_t sw = so ^ ((so >> 3) & 0x70);
                    cpasync16(tb + sw, src + (krow0 + T0 + r) * 2048 + hbyte + c16);
                }
            }
            CP_COMMIT();
            if (tid < 64)
                mfbase[buf * 64 + tid] = mask[(size_t)b * TK + T0 + tid] ? 1.f : 0.f;
        }
    }

    float rinv0 = 1.f / lrow0;
    float rinv1 = 1.f / lrow1;
    int grow = (int)qrow0 + wid * 16 + (lane >> 2);
    int col0 = h * 64 + (lane & 3) * 2;
    #pragma unroll
    for (int f = 0; f < 8; f++) {
        int cc = col0 + 8 * f;
        size_t off0 = (size_t)grow * DD + cc;
        size_t off1 = (size_t)(grow + 8) * DD + cc;
        *(__half2*)(Oh + off0) = __floats2half2_rn(O[f][0] * rinv0, O[f][1] * rinv0);
        *(__half2*)(Oh + off1) = __floats2half2_rn(O[f][2] * rinv1, O[f][3] * rinv1);
    }
}

// ---------------------------------------------------------------------------
// Launch
// ---------------------------------------------------------------------------
extern "C" void kernel_launch(void* const* d_in, const int* in_sizes, int n_in,
                              void* d_out, int out_size) {
    const float* x      = (const float*)d_in[0];
    const float* y      = (const float*)d_in[1];
    const int*   mask   = (const int*)d_in[2];
    const float* ln1_g  = (const float*)d_in[3];
    const float* ln1_b  = (const float*)d_in[4];
    const float* ln2_g  = (const float*)d_in[5];
    const float* ln2_b  = (const float*)d_in[6];
    const float* q_w    = (const float*)d_in[7];
    const float* q_b    = (const float*)d_in[8];
    const float* k_w    = (const float*)d_in[9];
    const float* k_b    = (const float*)d_in[10];
    const float* v_w    = (const float*)d_in[11];
    const float* v_b    = (const float*)d_in[12];
    const float* o_w    = (const float*)d_in[13];
    const float* o_b    = (const float*)d_in[14];
    const float* mln1_g = (const float*)d_in[15];
    const float* mln1_b = (const float*)d_in[16];
    const float* l1_w   = (const float*)d_in[17];
    const float* l1_b   = (const float*)d_in[18];
    const float* mln2_g = (const float*)d_in[19];
    const float* mln2_b = (const float*)d_in[20];
    const float* l2_w   = (const float*)d_in[21];
    const float* l2_b   = (const float*)d_in[22];
    float* out = (float*)d_out;

    float *x2, *hbuf;
    __half *xh, *yh, *ph, *bhi, *blo, *qh, *kh, *vh;
    cudaGetSymbolAddress((void**)&x2,   g_x2);
    cudaGetSymbolAddress((void**)&hbuf, g_h);
    cudaGetSymbolAddress((void**)&xh,   g_xh);
    cudaGetSymbolAddress((void**)&yh,   g_yh);
    cudaGetSymbolAddress((void**)&ph,   g_ph);
    cudaGetSymbolAddress((void**)&bhi,  g_bhi);
    cudaGetSymbolAddress((void**)&blo,  g_blo);
    cudaGetSymbolAddress((void**)&qh,   g_qh);
    cudaGetSymbolAddress((void**)&kh,   g_kh);
    cudaGetSymbolAddress((void**)&vh,   g_vh);

    cudaFuncSetAttribute(gemm_hmma, cudaFuncAttributeMaxDynamicSharedMemorySize, GT_SMEM);
    cudaFuncSetAttribute(flash_kernel, cudaFuncAttributeMaxDynamicSharedMemorySize, FA_SMEM);

    dim3 gemmGrid(8, 16);                       // N/128, M/256 = 128 CTAs
    dim3 tGrid(32, 32);
    dim3 tBlock(32, 8);

    // 1) pre-norms -> fp16
    ln_relu_h_kernel<<<MROWS, 256>>>(x, ln1_g, ln1_b, xh);
    ln_relu_h_kernel<<<BB * TK, 256>>>(y, ln2_g, ln2_b, yh);

    // 2) q/k/v projections -> fp16
    transpose_split_kernel<<<tGrid, tBlock>>>(q_w, bhi, blo);
    gemm_hmma<<<gemmGrid, GT_THREADS, GT_SMEM>>>(xh, bhi, blo, q_b, nullptr,
                                                 nullptr, qh);
    transpose_split_kernel<<<tGrid, tBlock>>>(k_w, bhi, blo);
    gemm_hmma<<<gemmGrid, GT_THREADS, GT_SMEM>>>(yh, bhi, blo, k_b, nullptr,
                                                 nullptr, kh);
    transpose_split_kernel<<<tGrid, tBlock>>>(v_w, bhi, blo);
    gemm_hmma<<<gemmGrid, GT_THREADS, GT_SMEM>>>(yh, bhi, blo, v_b, nullptr,
                                                 nullptr, vh);

    // 3) fused flash attention -> fp16
    flash_kernel<<<dim3(8, BH), 256, FA_SMEM>>>(qh, kh, vh, mask, ph);

    // 4) output proj + residual (fp32 out)
    transpose_split_kernel<<<tGrid, tBlock>>>(o_w, bhi, blo);
    gemm_hmma<<<gemmGrid, GT_THREADS, GT_SMEM>>>(ph, bhi, blo, o_b, x,
                                                 x2, nullptr);

    // 5) MLP
    ln_relu_h_kernel<<<MROWS, 256>>>(x2, mln1_g, mln1_b, xh);
    transpose_split_kernel<<<tGrid, tBlock>>>(l1_w, bhi, blo);
    gemm_hmma<<<gemmGrid, GT_THREADS, GT_SMEM>>>(xh, bhi, blo, l1_b, nullptr,
                                                 hbuf, nullptr);

    ln_relu_h_kernel<<<MROWS, 256>>>(hbuf, mln2_g, mln2_b, yh);
    transpose_split_kernel<<<tGrid, tBlock>>>(l2_w, bhi, blo);
    gemm_hmma<<<gemmGrid, GT_THREADS, GT_SMEM>>>(yh, bhi, blo, l2_b, nullptr,
                                                 out, nullptr);
}

// round 9
// speedup vs baseline: 2.1435x; 1.3801x over previous
#include <cuda_runtime.h>
#include <cuda_fp16.h>
#include <math.h>
#include <stdint.h>

// ---------------------------------------------------------------------------
// Problem dims (fixed)
// ---------------------------------------------------------------------------
#define BB 4
#define TQ 1024
#define TK 1024
#define DD 1024
#define HH 16
#define DK 64
#define DV 64
#define MROWS (BB * TQ)          // 4096
#define BH (BB * HH)             // 64

// ---------------------------------------------------------------------------
// Scratch (device globals — no allocations allowed)
// ---------------------------------------------------------------------------
__device__ float g_x2 [MROWS * DD];
__device__ float g_h  [MROWS * DD];
// fp16 activation buffers
__device__ __half g_xh[MROWS * DD];    // ln1(x) / mln1(x2) reuse
__device__ __half g_yh[MROWS * DD];    // ln2(y) / mln2(h) reuse
__device__ __half g_ph[MROWS * DD];    // flash output
// weight (transposed) fp16
__device__ __half g_bh[DD * DD];
// q/k/v fp16 (written directly by GEMM epilogue)
__device__ __half g_qh[MROWS * DD];
__device__ __half g_kh[MROWS * DD];
__device__ __half g_vh[MROWS * DD];

// ---------------------------------------------------------------------------
// PTX helpers (sm_80+ baseline features only)
// ---------------------------------------------------------------------------
__device__ __forceinline__ uint32_t smem_u32(const void* p) {
    uint32_t a;
    asm("{ .reg .u64 t; cvta.to.shared.u64 t, %1; cvt.u32.u64 %0, t; }" : "=r"(a) : "l"(p));
    return a;
}
__device__ __forceinline__ void cpasync16(uint32_t dst, const void* src) {
    asm volatile("cp.async.cg.shared.global [%0], [%1], 16;" :: "r"(dst), "l"(src) : "memory");
}
#define CP_COMMIT() asm volatile("cp.async.commit_group;" ::: "memory")
#define CP_WAIT(n)  asm volatile("cp.async.wait_group %0;" :: "n"(n) : "memory")

__device__ __forceinline__ void ldm4(uint32_t* r, uint32_t addr) {
    asm volatile("ldmatrix.sync.aligned.m8n8.x4.shared.b16 {%0,%1,%2,%3}, [%4];"
        : "=r"(r[0]), "=r"(r[1]), "=r"(r[2]), "=r"(r[3]) : "r"(addr));
}
__device__ __forceinline__ void ldm4t(uint32_t* r, uint32_t addr) {
    asm volatile("ldmatrix.sync.aligned.m8n8.x4.trans.shared.b16 {%0,%1,%2,%3}, [%4];"
        : "=r"(r[0]), "=r"(r[1]), "=r"(r[2]), "=r"(r[3]) : "r"(addr));
}
// fp16 mma, fp32 accumulate
__device__ __forceinline__ void mma16816h(float* d, const uint32_t* a, const uint32_t* b) {
    asm volatile("mma.sync.aligned.m16n8k16.row.col.f32.f16.f16.f32 "
        "{%0,%1,%2,%3}, {%4,%5,%6,%7}, {%8,%9}, {%0,%1,%2,%3};"
        : "+f"(d[0]), "+f"(d[1]), "+f"(d[2]), "+f"(d[3])
        : "r"(a[0]), "r"(a[1]), "r"(a[2]), "r"(a[3]), "r"(b[0]), "r"(b[1]));
}

// ---------------------------------------------------------------------------
// LayerNorm + ReLU -> single fp16
// ---------------------------------------------------------------------------
__global__ void ln_relu_h_kernel(const float* __restrict__ in,
                                 const float* __restrict__ gamma,
                                 const float* __restrict__ beta,
                                 __half* __restrict__ out) {
    int row = blockIdx.x;
    int tid = threadIdx.x;
    const float* p = in + (size_t)row * DD + tid * 4;
    float4 xv = *(const float4*)p;

    float s  = xv.x + xv.y + xv.z + xv.w;
    float ss = xv.x*xv.x + xv.y*xv.y + xv.z*xv.z + xv.w*xv.w;
    #pragma unroll
    for (int off = 16; off > 0; off >>= 1) {
        s  += __shfl_xor_sync(0xffffffffu, s,  off);
        ss += __shfl_xor_sync(0xffffffffu, ss, off);
    }
    __shared__ float sbuf[8], ssbuf[8];
    __shared__ float smean, sinv;
    int lane = tid & 31, warp = tid >> 5;
    if (lane == 0) { sbuf[warp] = s; ssbuf[warp] = ss; }
    __syncthreads();
    if (tid == 0) {
        float ts = 0.f, tss = 0.f;
        #pragma unroll
        for (int i = 0; i < 8; i++) { ts += sbuf[i]; tss += ssbuf[i]; }
        float mean = ts * (1.0f / DD);
        float var  = tss * (1.0f / DD) - mean * mean;
        smean = mean;
        sinv  = rsqrtf(var + 1e-5f);
    }
    __syncthreads();
    float m = smean, inv = sinv;

    int c = tid * 4;
    float4 g4 = *(const float4*)(gamma + c);
    float4 b4 = *(const float4*)(beta  + c);
    float o0 = fmaxf(0.f, (xv.x - m) * inv * g4.x + b4.x);
    float o1 = fmaxf(0.f, (xv.y - m) * inv * g4.y + b4.y);
    float o2 = fmaxf(0.f, (xv.z - m) * inv * g4.z + b4.z);
    float o3 = fmaxf(0.f, (xv.w - m) * inv * g4.w + b4.w);

    size_t base = (size_t)row * DD + c;
    *(__half2*)(out + base)     = __floats2half2_rn(o0, o1);
    *(__half2*)(out + base + 2) = __floats2half2_rn(o2, o3);
}

// ---------------------------------------------------------------------------
// Transpose: W[K,N] fp32 -> Wt [N,K] fp16
// ---------------------------------------------------------------------------
__global__ void transpose_h_kernel(const float* __restrict__ W,
                                   __half* __restrict__ hi) {
    __shared__ float tile[32][33];
    int tx = threadIdx.x, ty = threadIdx.y;          // 32 x 8
    int n0 = blockIdx.x * 32, k0 = blockIdx.y * 32;
    #pragma unroll
    for (int i = 0; i < 4; i++) {
        int kr = ty + i * 8;
        tile[kr][tx] = W[(size_t)(k0 + kr) * DD + n0 + tx];
    }
    __syncthreads();
    #pragma unroll
    for (int i = 0; i < 4; i++) {
        int nr = ty + i * 8;
        hi[(size_t)(n0 + nr) * DD + k0 + tx] = __float2half_rn(tile[tx][nr]);
    }
}

// ---------------------------------------------------------------------------
// HMMA GEMM (fp16, single-term): C = A @ B^T (+bias, +res)
// A: fp16 [M,K]; B: fp16 [N,K].
// CTA 256x128, BK=64, double-buffered cp.async, 16 warps (4M x 4N), wtile 64x32.
// smem: A[2]=64K  B[2]=32K -> 96K.  Grid (8,16) = 128 CTAs = one wave.
// ---------------------------------------------------------------------------
#define GA_OFF(buf)  ((buf) * 32768)
#define GB_OFF(buf)  (65536 + (buf) * 16384)
#define GT_SMEM 98304
#define GT_THREADS 512

struct GPtrs { const char *a, *b; };

__device__ __forceinline__ void gt_load_chunk(uint32_t sb, int buf,
                                              const GPtrs& g, int chunk, int tid) {
    size_t kbyte = (size_t)chunk * 128;
    // A tile: 256 rows x 128B = 2048 x 16B
    {
        uint32_t base = sb + GA_OFF(buf);
        #pragma unroll
        for (int it = 0; it < 4; it++) {
            int idx = tid + it * GT_THREADS;        // 0..2047
            int r = idx >> 3;
            int c16 = idx & 7;
            uint32_t so = (uint32_t)(r * 128 + c16 * 16);
            uint32_t sw = so ^ ((so >> 3) & 0x70);
            cpasync16(base + sw, g.a + (size_t)r * 2048 + kbyte + c16 * 16);
        }
    }
    // B tile: 128 rows x 128B = 1024 x 16B
    {
        uint32_t base = sb + GB_OFF(buf);
        #pragma unroll
        for (int it = 0; it < 2; it++) {
            int idx = tid + it * GT_THREADS;        // 0..1023
            int r = idx >> 3;
            int c16 = idx & 7;
            uint32_t so = (uint32_t)(r * 128 + c16 * 16);
            uint32_t sw = so ^ ((so >> 3) & 0x70);
            cpasync16(base + sw, g.b + (size_t)r * 2048 + kbyte + c16 * 16);
        }
    }
}

__global__ void __launch_bounds__(GT_THREADS, 1)
gemm_hmma(const __half* __restrict__ A, const __half* __restrict__ B,
          const float* __restrict__ bias, const float* __restrict__ res,
          float* __restrict__ C, __half* __restrict__ Ch) {
    extern __shared__ char smem[];
    uint32_t sb = smem_u32(smem);
    int tid = threadIdx.x;
    int lane = tid & 31;
    int wid = tid >> 5;              // 0..15
    int wm = wid & 3;                // 0..3 (M, 64 rows each)
    int wn = wid >> 2;               // 0..3 (N, 32 cols each)

    int n0 = blockIdx.x * 128;
    int m0 = blockIdx.y * 256;

    GPtrs g;
    g.a = (const char*)(A + (size_t)m0 * DD);
    g.b = (const char*)(B + (size_t)n0 * DD);

    float acc[4][4][4];
    #pragma unroll
    for (int i = 0; i < 4; i++)
        #pragma unroll
        for (int j = 0; j < 4; j++)
            #pragma unroll
            for (int r = 0; r < 4; r++) acc[i][j][r] = 0.f;

    uint32_t aRow = (uint32_t)(wm * 64 + (lane & 15));
    uint32_t xorb = (uint32_t)((lane & 7) * 16);
    uint32_t aHi  = (uint32_t)(((lane >> 4) & 1) * 16);
    uint32_t bRow = (uint32_t)(wn * 32 + ((lane >> 4) & 1) * 8 + (lane & 7));
    uint32_t bHi  = (uint32_t)(((lane >> 3) & 1) * 16);

    gt_load_chunk(sb, 0, g, 0, tid);
    CP_COMMIT();

    #pragma unroll 1
    for (int c = 0; c < 16; c++) {
        int buf = c & 1;
        if (c < 15) {
            gt_load_chunk(sb, buf ^ 1, g, c + 1, tid);
            CP_COMMIT();
            CP_WAIT(1);
        } else {
            CP_WAIT(0);
        }
        __syncthreads();

        uint32_t tA = sb + GA_OFF(buf);
        uint32_t tB = sb + GB_OFF(buf);

        #pragma unroll
        for (int ks = 0; ks < 4; ks++) {
            uint32_t ka = ((uint32_t)(ks * 32) + aHi) ^ xorb;
            uint32_t kb = ((uint32_t)(ks * 32) + bHi) ^ xorb;

            uint32_t Af[4][4], Bf[2][4];
            #pragma unroll
            for (int i = 0; i < 4; i++) {
                uint32_t ro = (aRow + 16 * i) * 128;
                ldm4(Af[i], tA + ro + ka);
            }
            #pragma unroll
            for (int jp = 0; jp < 2; jp++) {
                uint32_t ro = (bRow + 16 * jp) * 128;
                ldm4(Bf[jp], tB + ro + kb);
            }
            #pragma unroll
            for (int i = 0; i < 4; i++) {
                #pragma unroll
                for (int j = 0; j < 4; j++) {
                    mma16816h(acc[i][j], Af[i], &Bf[j >> 1][(j & 1) * 2]);
                }
            }
        }
        __syncthreads();
    }

    int rbase = m0 + wm * 64 + (lane >> 2);
    int cbase = n0 + wn * 32 + (lane & 3) * 2;
    #pragma unroll
    for (int j = 0; j < 4; j++) {
        int cc = cbase + 8 * j;
        float2 b2 = *(const float2*)(bias + cc);
        #pragma unroll
        for (int i = 0; i < 4; i++) {
            int r = rbase + 16 * i;
            float2 o0 = {acc[i][j][0] + b2.x, acc[i][j][1] + b2.y};
            float2 o1 = {acc[i][j][2] + b2.x, acc[i][j][3] + b2.y};
            size_t off0 = (size_t)r * DD + cc;
            size_t off1 = (size_t)(r + 8) * DD + cc;
            if (Ch) {
                *(__half2*)(Ch + off0) = __floats2half2_rn(o0.x, o0.y);
                *(__half2*)(Ch + off1) = __floats2half2_rn(o1.x, o1.y);
            } else {
                if (res) {
                    float2 r0 = *(const float2*)(res + off0);
                    float2 r1 = *(const float2*)(res + off1);
                    o0.x += r0.x; o0.y += r0.y;
                    o1.x += r1.x; o1.y += r1.y;
                }
                *(float2*)(C + off0) = o0;
                *(float2*)(C + off1) = o1;
            }
        }
    }
}

// ---------------------------------------------------------------------------
// Fused flash attention (single fp16 HMMA). Output single fp16.
// Grid: (TQ/128 = 8, BH = 64), 256 threads (8 warps, 16 q-rows each).
// smem: Q 16K | 2 x [K 8K, V 8K] | mask 512B  -> ~49.7K; 2 CTAs/SM.
// ---------------------------------------------------------------------------
#define FA_KBUF(buf) (16384 + (buf) * 16384)
#define FA_SMEM      (49152 + 512)

__global__ void __launch_bounds__(256, 2)
flash_kernel(const __half* __restrict__ Qh, const __half* __restrict__ Kh,
             const __half* __restrict__ Vh, const int* __restrict__ mask,
             __half* __restrict__ Oh) {
    extern __shared__ char smem[];
    uint32_t sb = smem_u32(smem);
    int tid = threadIdx.x;
    int lane = tid & 31, wid = tid >> 5;
    int qtile = blockIdx.x;
    int bh = blockIdx.y;
    int b = bh >> 4, h = bh & 15;

    size_t qrow0 = (size_t)b * TQ + (size_t)qtile * 128;
    size_t krow0 = (size_t)b * TK;
    uint32_t hbyte = (uint32_t)h * 128;

    uint32_t sQ = sb;
    float* mfbase = (float*)(smem + 49152);

    // Q tile: 128 rows x 128B = 1024 x 16B
    {
        const char* gq = (const char*)Qh;
        #pragma unroll
        for (int it = 0; it < 4; it++) {
            int idx = tid + it * 256;
            int r = idx >> 3, c16 = (idx & 7) * 16;
            uint32_t so = (uint32_t)(r * 128 + c16);
            uint32_t sw = so ^ ((so >> 3) & 0x70);
            cpasync16(sQ + sw, gq + (qrow0 + r) * 2048 + hbyte + c16);
        }
    }

    const char* gK = (const char*)Kh;
    const char* gV = (const char*)Vh;

    #pragma unroll
    for (int pre = 0; pre < 2; pre++) {
        uint32_t base = sb + FA_KBUF(pre);
        #pragma unroll
        for (int t = 0; t < 2; t++) {
            const char* src = t ? gV : gK;
            uint32_t tb = base + t * 8192;
            #pragma unroll
            for (int it = 0; it < 2; it++) {
                int idx = tid + it * 256;
                int r = idx >> 3, c16 = (idx & 7) * 16;
                uint32_t so = (uint32_t)(r * 128 + c16);
                uint32_t sw = so ^ ((so >> 3) & 0x70);
                cpasync16(tb + sw, src + (krow0 + pre * 64 + r) * 2048 + hbyte + c16);
            }
        }
        CP_COMMIT();
        if (tid < 64)
            mfbase[pre * 64 + tid] = mask[(size_t)b * TK + pre * 64 + tid] ? 1.f : 0.f;
    }

    uint32_t xorb = (uint32_t)((lane & 7) * 16);
    uint32_t aHi  = (uint32_t)(((lane >> 4) & 1) * 16);
    uint32_t kRowBase = 8 * ((lane >> 4) & 1) + (lane & 7);
    uint32_t kColHalf = 16 * ((lane >> 3) & 1);
    uint32_t vRowBase = 8 * ((lane >> 3) & 1) + (lane & 7);
    uint32_t vColHalf = 16 * ((lane >> 4) & 1);

    float O[8][4];
    #pragma unroll
    for (int f = 0; f < 8; f++)
        #pragma unroll
        for (int r = 0; r < 4; r++) O[f][r] = 0.f;
    float mrow0 = -INFINITY, mrow1 = -INFINITY;
    float lrow0 = 0.f, lrow1 = 0.f;
    uint32_t QF[4][4];

    #pragma unroll 1
    for (int c = 0; c < 16; c++) {
        int buf = c & 1;
        if (c < 15) { CP_WAIT(1); } else { CP_WAIT(0); }
        __syncthreads();

        if (c == 0) {
            #pragma unroll
            for (int ks = 0; ks < 4; ks++) {
                uint32_t row = (uint32_t)(wid * 16 + (lane & 15));
                uint32_t col = ((uint32_t)(ks * 32) + aHi) ^ xorb;
                ldm4(QF[ks], sQ + row * 128 + col);
            }
        }

        uint32_t sK = sb + FA_KBUF(buf);
        uint32_t sV = sK + 8192;
        const float* mf = mfbase + buf * 64;

        float S[8][4];
        #pragma unroll
        for (int n = 0; n < 8; n++)
            #pragma unroll
            for (int r = 0; r < 4; r++) S[n][r] = 0.f;

        #pragma unroll
        for (int ks = 0; ks < 4; ks++) {
            uint32_t col = ((uint32_t)(ks * 32) + kColHalf) ^ xorb;
            #pragma unroll
            for (int np = 0; np < 4; np++) {
                uint32_t KF[4];
                uint32_t ro = (np * 16 + kRowBase) * 128;
                ldm4(KF, sK + ro + col);
                mma16816h(S[np*2],   QF[ks], KF);
                mma16816h(S[np*2+1], QF[ks], KF + 2);
            }
        }

        #pragma unroll
        for (int n = 0; n < 8; n++) {
            int j = 8 * n + (lane & 3) * 2;
            float mk0 = mf[j], mk1 = mf[j + 1];
            S[n][0] = (mk0 != 0.f) ? S[n][0] * 0.125f : -1e30f;
            S[n][1] = (mk1 != 0.f) ? S[n][1] * 0.125f : -1e30f;
            S[n][2] = (mk0 != 0.f) ? S[n][2] * 0.125f : -1e30f;
            S[n][3] = (mk1 != 0.f) ? S[n][3] * 0.125f : -1e30f;
        }

        float cm0 = -INFINITY, cm1 = -INFINITY;
        #pragma unroll
        for (int n = 0; n < 8; n++) {
            cm0 = fmaxf(cm0, fmaxf(S[n][0], S[n][1]));
            cm1 = fmaxf(cm1, fmaxf(S[n][2], S[n][3]));
        }
        cm0 = fmaxf(cm0, __shfl_xor_sync(0xffffffffu, cm0, 1));
        cm0 = fmaxf(cm0, __shfl_xor_sync(0xffffffffu, cm0, 2));
        cm1 = fmaxf(cm1, __shfl_xor_sync(0xffffffffu, cm1, 1));
        cm1 = fmaxf(cm1, __shfl_xor_sync(0xffffffffu, cm1, 2));

        float mn0 = fmaxf(mrow0, cm0);
        float mn1 = fmaxf(mrow1, cm1);
        float al0 = __expf(mrow0 - mn0);
        float al1 = __expf(mrow1 - mn1);
        mrow0 = mn0; mrow1 = mn1;

        uint32_t P[4][4];
        float sum0 = 0.f, sum1 = 0.f;
        #pragma unroll
        for (int n = 0; n < 8; n++) {
            float p0 = __expf(S[n][0] - mn0);
            float p1 = __expf(S[n][1] - mn0);
            float p2 = __expf(S[n][2] - mn1);
            float p3 = __expf(S[n][3] - mn1);
            sum0 += p0 + p1;
            sum1 += p2 + p3;
            __half2 h01 = __floats2half2_rn(p0, p1);
            __half2 h23 = __floats2half2_rn(p2, p3);
            int kk = n >> 1, base = (n & 1) * 2;
            P[kk][base]     = *(uint32_t*)&h01;
            P[kk][base + 1] = *(uint32_t*)&h23;
        }
        sum0 += __shfl_xor_sync(0xffffffffu, sum0, 1);
        sum0 += __shfl_xor_sync(0xffffffffu, sum0, 2);
        sum1 += __shfl_xor_sync(0xffffffffu, sum1, 1);
        sum1 += __shfl_xor_sync(0xffffffffu, sum1, 2);
        lrow0 = lrow0 * al0 + sum0;
        lrow1 = lrow1 * al1 + sum1;
        #pragma unroll
        for (int f = 0; f < 8; f++) {
            O[f][0] *= al0; O[f][1] *= al0;
            O[f][2] *= al1; O[f][3] *= al1;
        }

        #pragma unroll
        for (int ks = 0; ks < 4; ks++) {
            uint32_t ro = (ks * 16 + vRowBase) * 128;
            #pragma unroll
            for (int dp = 0; dp < 4; dp++) {
                uint32_t col = ((uint32_t)(dp * 32) + vColHalf) ^ xorb;
                uint32_t VF[4];
                ldm4t(VF, sV + ro + col);
                mma16816h(O[dp*2],   P[ks], VF);
                mma16816h(O[dp*2+1], P[ks], VF + 2);
            }
        }

        __syncthreads();
        if (c < 14) {
            int T0 = (c + 2) * 64;
            uint32_t base = sb + FA_KBUF(buf);
            #pragma unroll
            for (int t = 0; t < 2; t++) {
                const char* src = t ? gV : gK;
                uint32_t tb = base + t * 8192;
                #pragma unroll
                for (int it = 0; it < 2; it++) {
                    int idx = tid + it * 256;
                    int r = idx >> 3, c16 = (idx & 7) * 16;
                    uint32_t so = (uint32_t)(r * 128 + c16);
                    uint32_t sw = so ^ ((so >> 3) & 0x70);
                    cpasync16(tb + sw, src + (krow0 + T0 + r) * 2048 + hbyte + c16);
                }
            }
            CP_COMMIT();
            if (tid < 64)
                mfbase[buf * 64 + tid] = mask[(size_t)b * TK + T0 + tid] ? 1.f : 0.f;
        }
    }

    float rinv0 = 1.f / lrow0;
    float rinv1 = 1.f / lrow1;
    int grow = (int)qrow0 + wid * 16 + (lane >> 2);
    int col0 = h * 64 + (lane & 3) * 2;
    #pragma unroll
    for (int f = 0; f < 8; f++) {
        int cc = col0 + 8 * f;
        size_t off0 = (size_t)grow * DD + cc;
        size_t off1 = (size_t)(grow + 8) * DD + cc;
        *(__half2*)(Oh + off0) = __floats2half2_rn(O[f][0] * rinv0, O[f][1] * rinv0);
        *(__half2*)(Oh + off1) = __floats2half2_rn(O[f][2] * rinv1, O[f][3] * rinv1);
    }
}

// ---------------------------------------------------------------------------
// Launch
// ---------------------------------------------------------------------------
extern "C" void kernel_launch(void* const* d_in, const int* in_sizes, int n_in,
                              void* d_out, int out_size) {
    const float* x      = (const float*)d_in[0];
    const float* y      = (const float*)d_in[1];
    const int*   mask   = (const int*)d_in[2];
    const float* ln1_g  = (const float*)d_in[3];
    const float* ln1_b  = (const float*)d_in[4];
    const float* ln2_g  = (const float*)d_in[5];
    const float* ln2_b  = (const float*)d_in[6];
    const float* q_w    = (const float*)d_in[7];
    const float* q_b    = (const float*)d_in[8];
    const float* k_w    = (const float*)d_in[9];
    const float* k_b    = (const float*)d_in[10];
    const float* v_w    = (const float*)d_in[11];
    const float* v_b    = (const float*)d_in[12];
    const float* o_w    = (const float*)d_in[13];
    const float* o_b    = (const float*)d_in[14];
    const float* mln1_g = (const float*)d_in[15];
    const float* mln1_b = (const float*)d_in[16];
    const float* l1_w   = (const float*)d_in[17];
    const float* l1_b   = (const float*)d_in[18];
    const float* mln2_g = (const float*)d_in[19];
    const float* mln2_b = (const float*)d_in[20];
    const float* l2_w   = (const float*)d_in[21];
    const float* l2_b   = (const float*)d_in[22];
    float* out = (float*)d_out;

    float *x2, *hbuf;
    __half *xh, *yh, *ph, *bh, *qh, *kh, *vh;
    cudaGetSymbolAddress((void**)&x2,   g_x2);
    cudaGetSymbolAddress((void**)&hbuf, g_h);
    cudaGetSymbolAddress((void**)&xh,   g_xh);
    cudaGetSymbolAddress((void**)&yh,   g_yh);
    cudaGetSymbolAddress((void**)&ph,   g_ph);
    cudaGetSymbolAddress((void**)&bh,   g_bh);
    cudaGetSymbolAddress((void**)&qh,   g_qh);
    cudaGetSymbolAddress((void**)&kh,   g_kh);
    cudaGetSymbolAddress((void**)&vh,   g_vh);

    cudaFuncSetAttribute(gemm_hmma, cudaFuncAttributeMaxDynamicSharedMemorySize, GT_SMEM);
    cudaFuncSetAttribute(flash_kernel, cudaFuncAttributeMaxDynamicSharedMemorySize, FA_SMEM);

    dim3 gemmGrid(8, 16);                       // N/128, M/256 = 128 CTAs
    dim3 tGrid(32, 32);
    dim3 tBlock(32, 8);

    // 1) pre-norms -> fp16
    ln_relu_h_kernel<<<MROWS, 256>>>(x, ln1_g, ln1_b, xh);
    ln_relu_h_kernel<<<BB * TK, 256>>>(y, ln2_g, ln2_b, yh);

    // 2) q/k/v projections -> fp16
    transpose_h_kernel<<<tGrid, tBlock>>>(q_w, bh);
    gemm_hmma<<<gemmGrid, GT_THREADS, GT_SMEM>>>(xh, bh, q_b, nullptr, nullptr, qh);
    transpose_h_kernel<<<tGrid, tBlock>>>(k_w, bh);
    gemm_hmma<<<gemmGrid, GT_THREADS, GT_SMEM>>>(yh, bh, k_b, nullptr, nullptr, kh);
    transpose_h_kernel<<<tGrid, tBlock>>>(v_w, bh);
    gemm_hmma<<<gemmGrid, GT_THREADS, GT_SMEM>>>(yh, bh, v_b, nullptr, nullptr, vh);

    // 3) fused flash attention -> fp16
    flash_kernel<<<dim3(8, BH), 256, FA_SMEM>>>(qh, kh, vh, mask, ph);

    // 4) output proj + residual (fp32 out)
    transpose_h_kernel<<<tGrid, tBlock>>>(o_w, bh);
    gemm_hmma<<<gemmGrid, GT_THREADS, GT_SMEM>>>(ph, bh, o_b, x, x2, nullptr);

    // 5) MLP
    ln_relu_h_kernel<<<MROWS, 256>>>(x2, mln1_g, mln1_b, xh);
    transpose_h_kernel<<<tGrid, tBlock>>>(l1_w, bh);
    gemm_hmma<<<gemmGrid, GT_THREADS, GT_SMEM>>>(xh, bh, l1_b, nullptr, hbuf, nullptr);

    ln_relu_h_kernel<<<MROWS, 256>>>(hbuf, mln2_g, mln2_b, yh);
    transpose_h_kernel<<<tGrid, tBlock>>>(l2_w, bh);
    gemm_hmma<<<gemmGrid, GT_THREADS, GT_SMEM>>>(yh, bh, l2_b, nullptr, out, nullptr);
}